// round 13
// baseline (speedup 1.0000x reference)
#include <cuda_runtime.h>
#include <cuda_fp16.h>
#include <cstdint>
#include <math.h>

#define D_MODEL 2048
#define N_EXP   64
#define TOP_K   8
#define SCALE   0.022097086912079608f
#define EPS     2e-6f
#define MAX_T   16384
#define CTA_TOK 64
#define NCHUNK  32            // 2048 / 64
#define WPITCH  160           // bytes per 64-half W smem row (bank-perfect LDS.64)
#define TPITCH  528           // bytes per 16x16 A-fragment tile (bank-rotated)
#define LROW    66
#define LOSCALE 1024.0f
#define INV_LOSCALE 0.0009765625f

// ---- device globals (no allocations allowed; zero-initialized at load) -----
__device__ int g_flag_count;   // 0 at call 1; reset by fixup ticket thereafter
__device__ int g_done_count;
__device__ int g_flags[MAX_T];

// ---- fp16 MMA ---------------------------------------------------------------
static __device__ __forceinline__ void mma16816(float* d, const uint32_t* a,
                                                uint32_t b0, uint32_t b1) {
    asm volatile(
        "mma.sync.aligned.m16n8k16.row.col.f32.f16.f16.f32 "
        "{%0,%1,%2,%3}, {%4,%5,%6,%7}, {%8,%9}, {%0,%1,%2,%3};"
        : "+f"(d[0]), "+f"(d[1]), "+f"(d[2]), "+f"(d[3])
        : "r"(a[0]), "r"(a[1]), "r"(a[2]), "r"(a[3]), "r"(b0), "r"(b1));
}

static __device__ __forceinline__ uint32_t cvt2(float a, float b) {
    __half2 h = __floats2half2_rn(a, b);
    return *reinterpret_cast<uint32_t*>(&h);
}
// hi fp16 pair + residual (x1024) fp16 pair
static __device__ __forceinline__ void split2(float a, float b,
                                              uint32_t& hi, uint32_t& lo) {
    __half2 h = __floats2half2_rn(a, b);
    hi = *reinterpret_cast<uint32_t*>(&h);
    float ra = (a - __half2float(h.x)) * LOSCALE;
    float rb = (b - __half2float(h.y)) * LOSCALE;
    lo = cvt2(ra, rb);
}

// ---------------------------------------------------------------------------
// Main: 3-pass fp16-split HMMA (xh*Wh + xh*Wl + xl*Wh; lo scaled x1024),
// A/W tiles staged fragment-permuted in dynamic SMEM, double buffered,
// fused top-9 / flag / softmax. CTA = 256 thr / 8 warps; CTA_TOK=64.
// ---------------------------------------------------------------------------
#define SM_AH(s)  ((s) * (16 * TPITCH))                         // 2 x 8448
#define SM_AL(s)  (16896 + (s) * (16 * TPITCH))                 // 2 x 8448
#define SM_WH(s)  (33792 + (s) * (64 * WPITCH))                 // 2 x 10240
#define SM_WL(s)  (54272 + (s) * (64 * WPITCH))                 // 2 x 10240
#define SM_BIAS   74752
#define SM_TOT    75008

__global__ void __launch_bounds__(256, 2)
router_mma_kernel(const float* __restrict__ x, const float* __restrict__ W,
                  const float* __restrict__ bias, float* __restrict__ out, int T)
{
    extern __shared__ __align__(16) char sm[];

    const int tid  = threadIdx.x;
    const int wid  = tid >> 5;
    const int lane = tid & 31;
    const int tg   = wid >> 1;
    const int eh   = wid & 1;
    const int tokBase = blockIdx.x * CTA_TOK;
    const int wtok = tokBase + tg * 16;

    float* bias_sm = reinterpret_cast<float*>(sm + SM_BIAS);
    if (tid < N_EXP) bias_sm[tid] = bias[tid];

    const int n4 = lane >> 2;
    const int q4 = lane & 3;
    const int cp2 = q4 << 1;

    // ---- A writer mapping (proven): 4 float4 per thread, coalesced ---------
    int arow[4], adst0[4], adst1[4];
#pragma unroll
    for (int j = 0; j < 4; j++) {
        int u  = tid + 256 * j;
        int r  = u >> 4;
        int k0 = (u & 15) * 4;
        int tgw = r >> 4, rr = r & 15, rA = rr & 7, hifl = rr >> 3;
        int ks = k0 >> 4, kk = k0 & 15, khi = kk >> 3, qa = (kk & 7) >> 1;
        arow[j]  = r;
        int tbase = (tgw * 4 + ks) * TPITCH + (hifl + khi * 2) * 4;
        adst0[j] = tbase + (rA * 4 + qa) * 16;
        adst1[j] = tbase + (rA * 4 + qa + 1) * 16;
    }
    const int ak0_0 = (tid & 15) * 4;

    const float* wgp = W + (size_t)(tid >> 2) * D_MODEL + (tid & 3) * 16;
    const int    wse = (tid >> 2) * WPITCH + (tid & 3) * 32;

    auto loadA = [&](int c, float4* av) {
#pragma unroll
        for (int j = 0; j < 4; j++)
            av[j] = *reinterpret_cast<const float4*>(
                x + (size_t)(tokBase + arow[j]) * D_MODEL + c * 64 + ak0_0);
    };
    auto storeA = [&](int s, const float4* av) {
#pragma unroll
        for (int j = 0; j < 4; j++) {
            uint32_t h01, l01, h23, l23;
            split2(av[j].x, av[j].y, h01, l01);
            split2(av[j].z, av[j].w, h23, l23);
            *reinterpret_cast<uint32_t*>(sm + SM_AH(s) + adst0[j]) = h01;
            *reinterpret_cast<uint32_t*>(sm + SM_AH(s) + adst1[j]) = h23;
            *reinterpret_cast<uint32_t*>(sm + SM_AL(s) + adst0[j]) = l01;
            *reinterpret_cast<uint32_t*>(sm + SM_AL(s) + adst1[j]) = l23;
        }
    };
    auto loadW = [&](int c, float4* wv) {
#pragma unroll
        for (int j = 0; j < 4; j++)
            wv[j] = *reinterpret_cast<const float4*>(wgp + c * 64 + j * 4);
    };
    // convert + fragment-permute + store hi/lo planes (16 elems -> 32B each)
    auto storeW = [&](int s, const float4* wv) {
        float f[16] = {wv[0].x, wv[0].y, wv[0].z, wv[0].w,
                       wv[1].x, wv[1].y, wv[1].z, wv[1].w,
                       wv[2].x, wv[2].y, wv[2].z, wv[2].w,
                       wv[3].x, wv[3].y, wv[3].z, wv[3].w};
        // permute: dst pair p takes src pair ((p&1)*4 + (p>>1)) of stride-2
        uint4 hA, lA;
        uint32_t* hp = reinterpret_cast<uint32_t*>(&hA);
        uint32_t* lp = reinterpret_cast<uint32_t*>(&lA);
#pragma unroll
        for (int p = 0; p < 4; p++) {       // first 8 dst halves: pairs 0..3
            int src = ((p & 1) << 3) + ((p >> 1) << 1);
            split2(f[src], f[src + 1], hp[p], lp[p]);
        }
        *reinterpret_cast<uint4*>(&sm[SM_WH(s) + wse]) = hA;
        *reinterpret_cast<uint4*>(&sm[SM_WL(s) + wse]) = lA;
#pragma unroll
        for (int p = 4; p < 8; p++) {       // second 8 dst halves: pairs 4..7
            int src = (((p & 1)) << 3) + ((p >> 1) << 1);
            split2(f[src], f[src + 1], hp[p - 4], lp[p - 4]);
        }
        *reinterpret_cast<uint4*>(&sm[SM_WH(s) + wse + 16]) = hA;
        *reinterpret_cast<uint4*>(&sm[SM_WL(s) + wse + 16]) = lA;
    };

    // prologue: stage chunk 0
    float4 av[4], wv[4];
    loadA(0, av);
    loadW(0, wv);
    storeA(0, av);
    storeW(0, wv);
    __syncthreads();

    float dh[4][4], dl[4][4];
#pragma unroll
    for (int j = 0; j < 4; j++)
#pragma unroll
        for (int q = 0; q < 4; q++) { dh[j][q] = 0.0f; dl[j][q] = 0.0f; }

    for (int c = 0; c < NCHUNK; c++) {
        const int buf = c & 1;

        if (c + 1 < NCHUNK) {
            loadA(c + 1, av);
            loadW(c + 1, wv);
        }

        const char* AH = sm + SM_AH(buf);
        const char* AL = sm + SM_AL(buf);
        const char* WH = sm + SM_WH(buf);
        const char* WL = sm + SM_WL(buf);
#pragma unroll
        for (int ks = 0; ks < 4; ks++) {
            const uint32_t aoff = (uint32_t)((tg * 4 + ks) * TPITCH + lane * 16);
            uint4 afh = *reinterpret_cast<const uint4*>(AH + aoff);
            uint4 afl = *reinterpret_cast<const uint4*>(AL + aoff);
            uint32_t ah[4] = {afh.x, afh.y, afh.z, afh.w};
            uint32_t al[4] = {afl.x, afl.y, afl.z, afl.w};
            const uint32_t cbase = (uint32_t)(ks * 32 + q4 * 8);
#pragma unroll
            for (int j = 0; j < 4; j++) {
                uint32_t ro = (uint32_t)((eh * 4 + j) * 8 + n4) * WPITCH + cbase;
                uint2 bh = *reinterpret_cast<const uint2*>(WH + ro);
                uint2 bl = *reinterpret_cast<const uint2*>(WL + ro);
                mma16816(dh[j], ah, bh.x, bh.y);   // xh * Wh
                mma16816(dl[j], ah, bl.x, bl.y);   // xh * Wl(*1024)
                mma16816(dl[j], al, bh.x, bh.y);   // xl(*1024) * Wh
            }
        }
        if (c + 1 < NCHUNK) {
            storeA(buf ^ 1, av);
            storeW(buf ^ 1, wv);
        }
        __syncthreads();
    }

    // ---- epilogue: combine hi+lo, spill logits, per-lane top-9 -------------
    float* lw = reinterpret_cast<float*>(sm + SM_WH(0)) + tg * 16 * LROW;
#pragma unroll
    for (int j = 0; j < 4; j++) {
        int col = eh * 32 + j * 8 + cp2;
        lw[n4 * LROW + col]           = dh[j][0] + dl[j][0] * INV_LOSCALE;
        lw[n4 * LROW + col + 1]       = dh[j][1] + dl[j][1] * INV_LOSCALE;
        lw[(n4 + 8) * LROW + col]     = dh[j][2] + dl[j][2] * INV_LOSCALE;
        lw[(n4 + 8) * LROW + col + 1] = dh[j][3] + dl[j][3] * INV_LOSCALE;
    }
    __syncthreads();

    if (eh == 0 && lane < 16) {
        const int tok = wtok + lane;
        const float* row = lw + lane * LROW;
        const float NEG = -3.0e38f;

        float val[9]; int idx[9];
#pragma unroll
        for (int j = 0; j < 9; j++) { val[j] = NEG; idx[j] = 0; }

#pragma unroll
        for (int e = 0; e < N_EXP; e++) {
            float cv = row[e] * SCALE + bias_sm[e];
            int   ci = e;
#pragma unroll
            for (int j = 0; j < 9; j++) {
                if (cv > val[j]) {
                    float tv = val[j]; val[j] = cv; cv = tv;
                    int   ti = idx[j]; idx[j] = ci; ci = ti;
                }
            }
        }

        float ming = val[0] - val[1];
#pragma unroll
        for (int j = 1; j < 8; j++) ming = fminf(ming, val[j] - val[j + 1]);

        float orig[TOP_K];
#pragma unroll
        for (int j = 0; j < TOP_K; j++) orig[j] = val[j] - bias_sm[idx[j]];
        float m = orig[0];
#pragma unroll
        for (int j = 1; j < TOP_K; j++) m = fmaxf(m, orig[j]);
        float ex[TOP_K], ssum = 0.0f;
#pragma unroll
        for (int j = 0; j < TOP_K; j++) { ex[j] = __expf(orig[j] - m); ssum += ex[j]; }
        float inv = 1.0f / ssum;

        float* wout = out + (size_t)tok * TOP_K;
        float* iout = out + (size_t)T * TOP_K + (size_t)tok * TOP_K;
#pragma unroll
        for (int j = 0; j < TOP_K; j++) { wout[j] = ex[j] * inv; iout[j] = (float)idx[j]; }

        if (ming < EPS) {
            int p = atomicAdd(&g_flag_count, 1);
            if (p < MAX_T) g_flags[p] = tok;
        }
    }
}

// ---------------------------------------------------------------------------
// Fixup v2 (proven in R12): 32 flagged tokens per batch; thread = 4 experts
// x 2 tokens. Exact reference-matching chain (serial FFMA ascending k,
// panels of 512 summed ascending). Last block resets flag counter.
// ---------------------------------------------------------------------------
#define FB 32
#define XPITCH 34
__global__ void __launch_bounds__(256) fixup_kernel(
    const float* __restrict__ x, const float* __restrict__ W,
    const float* __restrict__ bias, float* __restrict__ out, int T)
{
    __shared__ __align__(16) float Wp[64][68];
    __shared__ __align__(16) float Xt[64][XPITCH];
    __shared__ float bias_f[N_EXP];

    const int t = threadIdx.x;
    if (t < N_EXP) bias_f[t] = bias[t];

    int F = g_flag_count;
    if (F > MAX_T) F = MAX_T;
    const int nb = (F + FB - 1) / FB;

    const int e0 = (t & 15) * 4;
    const int tq = t >> 4;

    const int sx_tok = t >> 3;
    const int sx_k0  = (t & 7) * 8;

    float* Lg = &Wp[0][0];

    for (int b = blockIdx.x; b < nb; b += gridDim.x) {
        float accT[2][4], accP[2][4];
#pragma unroll
        for (int i = 0; i < 2; i++)
#pragma unroll
            for (int q = 0; q < 4; q++) { accT[i][q] = 0.f; accP[i][q] = 0.f; }

        for (int kc = 0; kc < 32; kc++) {
            __syncthreads();
            {
                int s2 = b * FB + sx_tok;
                int gt = g_flags[(s2 < F) ? s2 : (F - 1)];
                const float* xp = x + (size_t)gt * D_MODEL + kc * 64 + sx_k0;
                float4 v0 = *reinterpret_cast<const float4*>(xp);
                float4 v1 = *reinterpret_cast<const float4*>(xp + 4);
                Xt[sx_k0 + 0][sx_tok] = v0.x; Xt[sx_k0 + 1][sx_tok] = v0.y;
                Xt[sx_k0 + 2][sx_tok] = v0.z; Xt[sx_k0 + 3][sx_tok] = v0.w;
                Xt[sx_k0 + 4][sx_tok] = v1.x; Xt[sx_k0 + 5][sx_tok] = v1.y;
                Xt[sx_k0 + 6][sx_tok] = v1.z; Xt[sx_k0 + 7][sx_tok] = v1.w;
            }
#pragma unroll
            for (int j = 0; j < 4; j++) {
                int idx = t + 256 * j;
                int xe  = idx >> 4;
                int kq  = (idx & 15) * 4;
                float4 w = *reinterpret_cast<const float4*>(
                    W + (size_t)xe * D_MODEL + kc * 64 + kq);
                Wp[kq + 0][xe] = w.x;
                Wp[kq + 1][xe] = w.y;
                Wp[kq + 2][xe] = w.z;
                Wp[kq + 3][xe] = w.w;
            }
            __syncthreads();
#pragma unroll 4
            for (int k = 0; k < 64; k++) {
                float4 wvv = *reinterpret_cast<const float4*>(&Wp[k][e0]);
                float2 xvv = *reinterpret_cast<const float2*>(&Xt[k][tq * 2]);
                accP[0][0] = __fmaf_rn(xvv.x, wvv.x, accP[0][0]);
                accP[0][1] = __fmaf_rn(xvv.x, wvv.y, accP[0][1]);
                accP[0][2] = __fmaf_rn(xvv.x, wvv.z, accP[0][2]);
                accP[0][3] = __fmaf_rn(xvv.x, wvv.w, accP[0][3]);
                accP[1][0] = __fmaf_rn(xvv.y, wvv.x, accP[1][0]);
                accP[1][1] = __fmaf_rn(xvv.y, wvv.y, accP[1][1]);
                accP[1][2] = __fmaf_rn(xvv.y, wvv.z, accP[1][2]);
                accP[1][3] = __fmaf_rn(xvv.y, wvv.w, accP[1][3]);
            }
            if ((kc & 7) == 7) {
#pragma unroll
                for (int i = 0; i < 2; i++)
#pragma unroll
                    for (int q = 0; q < 4; q++) {
                        accT[i][q] = __fadd_rn(accT[i][q], accP[i][q]);
                        accP[i][q] = 0.0f;
                    }
            }
        }
        __syncthreads();
#pragma unroll
        for (int i = 0; i < 2; i++)
#pragma unroll
            for (int q = 0; q < 4; q++)
                Lg[(tq * 2 + i) * 66 + e0 + q] = __fmul_rn(accT[i][q], SCALE);
        __syncthreads();

        if (t < FB && b * FB + t < F) {
            const int tok = g_flags[b * FB + t];
            const float* row = &Lg[t * 66];
            unsigned long long used = 0ull;
            int sel[TOP_K]; float sl[TOP_K];
            for (int k = 0; k < TOP_K; k++) {
                float best = -3.0e38f; int bi = 0;
                for (int e = 0; e < N_EXP; e++) {
                    if ((used >> e) & 1ull) continue;
                    float bv = __fadd_rn(row[e], bias_f[e]);
                    if (bv > best) { best = bv; bi = e; }
                }
                sel[k] = bi; sl[k] = row[bi];
                used |= (1ull << bi);
            }
            float m = sl[0];
            for (int k = 1; k < TOP_K; k++) m = fmaxf(m, sl[k]);
            float ex[TOP_K], s = 0.0f;
            for (int k = 0; k < TOP_K; k++) { ex[k] = __expf(sl[k] - m); s += ex[k]; }
            float inv = 1.0f / s;
            for (int k = 0; k < TOP_K; k++) {
                out[(size_t)tok * TOP_K + k] = ex[k] * inv;
                out[(size_t)T * TOP_K + (size_t)tok * TOP_K + k] = (float)sel[k];
            }
        }
        __syncthreads();
    }

    __syncthreads();
    if (t == 0) {
        __threadfence();
        int ticket = atomicAdd(&g_done_count, 1);
        if (ticket == (int)gridDim.x - 1) {
            g_flag_count = 0;
            g_done_count = 0;
            __threadfence();
        }
    }
}

// ---------------------------------------------------------------------------
extern "C" void kernel_launch(void* const* d_in, const int* in_sizes, int n_in,
                              void* d_out, int out_size)
{
    const float* x    = (const float*)d_in[0];
    const float* W    = (const float*)d_in[1];
    const float* bias = (const float*)d_in[2];
    float* out        = (float*)d_out;

    int T = in_sizes[0] / D_MODEL;  // 16384

    cudaFuncSetAttribute(router_mma_kernel,
                         cudaFuncAttributeMaxDynamicSharedMemorySize, SM_TOT);
    router_mma_kernel<<<T / CTA_TOK, 256, SM_TOT>>>(x, W, bias, out, T);
    fixup_kernel<<<296, 256>>>(x, W, bias, out, T);
}

// round 14
// speedup vs baseline: 1.3619x; 1.3619x over previous
#include <cuda_runtime.h>
#include <cuda_fp16.h>
#include <cstdint>
#include <math.h>

#define D_MODEL 2048
#define N_EXP   64
#define TOP_K   8
#define SCALE   0.022097086912079608f
#define EPS     4.2e-5f
#define MAX_T   16384
#define CTA_TOK 64
#define NCHUNK  32            // 2048 / 64
#define WPITCH  160           // bytes per 64-half W smem row (bank-perfect LDS.64)
#define TPITCH  528           // bytes per 16x16 A-fragment tile (bank-rotated)
#define LROW    66

// ---- device globals (no allocations allowed; zero-initialized at load) -----
__device__ int   g_flag_count;   // 0 at call 1; reset by combine ticket after
__device__ int   g_done_count;
__device__ int   g_flags[MAX_T];
// panel partials: [batch(<=512)][tok 32][panel 4][exp 64]
__device__ float g_partial[(MAX_T / 32) * 32 * 4 * 64];

// ---- fp16 MMA ---------------------------------------------------------------
static __device__ __forceinline__ void mma16816(float* d, const uint32_t* a,
                                                uint32_t b0, uint32_t b1) {
    asm volatile(
        "mma.sync.aligned.m16n8k16.row.col.f32.f16.f16.f32 "
        "{%0,%1,%2,%3}, {%4,%5,%6,%7}, {%8,%9}, {%0,%1,%2,%3};"
        : "+f"(d[0]), "+f"(d[1]), "+f"(d[2]), "+f"(d[3])
        : "r"(a[0]), "r"(a[1]), "r"(a[2]), "r"(a[3]), "r"(b0), "r"(b1));
}

static __device__ __forceinline__ uint32_t cvt2(float a, float b) {
    __half2 h = __floats2half2_rn(a, b);
    return *reinterpret_cast<uint32_t*>(&h);
}

// ---------------------------------------------------------------------------
// Main (R12 proven, unchanged): x(fp16) x W(fp16, converted in-kernel) HMMA,
// A/W staged fragment-permuted, fused top-9 / flag / softmax.
// ---------------------------------------------------------------------------
#define SM_A(s)  ((s) * (16 * TPITCH))
#define SM_W(s)  (2 * 16 * TPITCH + (s) * (64 * WPITCH))
#define SM_BIAS  (2 * 16 * TPITCH + 2 * 64 * WPITCH)
#define SM_TOT   (SM_BIAS + 256)

__global__ void __launch_bounds__(256, 2)
router_mma_kernel(const float* __restrict__ x, const float* __restrict__ W,
                  const float* __restrict__ bias, float* __restrict__ out, int T)
{
    __shared__ __align__(16) char sm[SM_TOT];

    const int tid  = threadIdx.x;
    const int wid  = tid >> 5;
    const int lane = tid & 31;
    const int tg   = wid >> 1;
    const int eh   = wid & 1;
    const int tokBase = blockIdx.x * CTA_TOK;
    const int wtok = tokBase + tg * 16;

    float* bias_sm = reinterpret_cast<float*>(sm + SM_BIAS);
    if (tid < N_EXP) bias_sm[tid] = bias[tid];

    const int n4 = lane >> 2;
    const int q4 = lane & 3;
    const int cp2 = q4 << 1;

    int arow[4], adst0[4], adst1[4];
#pragma unroll
    for (int j = 0; j < 4; j++) {
        int u  = tid + 256 * j;
        int r  = u >> 4;
        int k0 = (u & 15) * 4;
        int tgw = r >> 4, rr = r & 15, rA = rr & 7, hifl = rr >> 3;
        int ks = k0 >> 4, kk = k0 & 15, khi = kk >> 3, qa = (kk & 7) >> 1;
        arow[j]  = r;
        int tbase = (tgw * 4 + ks) * TPITCH + (hifl + khi * 2) * 4;
        adst0[j] = tbase + (rA * 4 + qa) * 16;
        adst1[j] = tbase + (rA * 4 + qa + 1) * 16;
    }
    const int ak0_0 = (tid & 15) * 4;

    const float* wgp = W + (size_t)(tid >> 2) * D_MODEL + (tid & 3) * 16;
    const int    wse = (tid >> 2) * WPITCH + (tid & 3) * 32;

    auto loadA = [&](int c, float4* av) {
#pragma unroll
        for (int j = 0; j < 4; j++)
            av[j] = *reinterpret_cast<const float4*>(
                x + (size_t)(tokBase + arow[j]) * D_MODEL + c * 64 + ak0_0);
    };
    auto storeA = [&](int s, const float4* av) {
#pragma unroll
        for (int j = 0; j < 4; j++) {
            *reinterpret_cast<uint32_t*>(sm + SM_A(s) + adst0[j]) =
                cvt2(av[j].x, av[j].y);
            *reinterpret_cast<uint32_t*>(sm + SM_A(s) + adst1[j]) =
                cvt2(av[j].z, av[j].w);
        }
    };
    auto loadW = [&](int c, float4* wv) {
#pragma unroll
        for (int j = 0; j < 4; j++)
            wv[j] = *reinterpret_cast<const float4*>(wgp + c * 64 + j * 4);
    };
    auto storeW = [&](int s, const float4* wv) {
        const float f0 = wv[0].x, f1 = wv[0].y, f2  = wv[0].z, f3  = wv[0].w;
        const float f4 = wv[1].x, f5 = wv[1].y, f6  = wv[1].z, f7  = wv[1].w;
        const float f8 = wv[2].x, f9 = wv[2].y, f10 = wv[2].z, f11 = wv[2].w;
        const float f12 = wv[3].x, f13 = wv[3].y, f14 = wv[3].z, f15 = wv[3].w;
        uint4 lo, hi;
        lo.x = cvt2(f0, f1);   lo.y = cvt2(f8, f9);
        lo.z = cvt2(f2, f3);   lo.w = cvt2(f10, f11);
        hi.x = cvt2(f4, f5);   hi.y = cvt2(f12, f13);
        hi.z = cvt2(f6, f7);   hi.w = cvt2(f14, f15);
        *reinterpret_cast<uint4*>(&sm[SM_W(s) + wse])      = lo;
        *reinterpret_cast<uint4*>(&sm[SM_W(s) + wse + 16]) = hi;
    };

    float4 av[4], wv[4];
    loadA(0, av);
    loadW(0, wv);
    storeA(0, av);
    storeW(0, wv);
    __syncthreads();

    float dh[4][4];
#pragma unroll
    for (int j = 0; j < 4; j++)
#pragma unroll
        for (int q = 0; q < 4; q++) dh[j][q] = 0.0f;

    for (int c = 0; c < NCHUNK; c++) {
        const int buf = c & 1;

        if (c + 1 < NCHUNK) {
            loadA(c + 1, av);
            loadW(c + 1, wv);
        }

        const char* AS = sm + SM_A(buf);
        const char* WH = sm + SM_W(buf);
#pragma unroll
        for (int ks = 0; ks < 4; ks++) {
            uint4 af = *reinterpret_cast<const uint4*>(
                AS + (tg * 4 + ks) * TPITCH + lane * 16);
            uint32_t a[4] = {af.x, af.y, af.z, af.w};
            const uint32_t cbase = (uint32_t)(ks * 32 + q4 * 8);
#pragma unroll
            for (int j = 0; j < 4; j++) {
                uint32_t ro = (uint32_t)((eh * 4 + j) * 8 + n4) * WPITCH + cbase;
                uint2 bh = *reinterpret_cast<const uint2*>(WH + ro);
                mma16816(dh[j], a, bh.x, bh.y);
            }
        }
        if (c + 1 < NCHUNK) {
            storeA(buf ^ 1, av);
            storeW(buf ^ 1, wv);
        }
        __syncthreads();
    }

    float* lw = reinterpret_cast<float*>(sm + SM_W(0)) + tg * 16 * LROW;
#pragma unroll
    for (int j = 0; j < 4; j++) {
        int col = eh * 32 + j * 8 + cp2;
        lw[n4 * LROW + col]           = dh[j][0];
        lw[n4 * LROW + col + 1]       = dh[j][1];
        lw[(n4 + 8) * LROW + col]     = dh[j][2];
        lw[(n4 + 8) * LROW + col + 1] = dh[j][3];
    }
    __syncthreads();

    if (eh == 0 && lane < 16) {
        const int tok = wtok + lane;
        const float* row = lw + lane * LROW;
        const float NEG = -3.0e38f;

        float val[9]; int idx[9];
#pragma unroll
        for (int j = 0; j < 9; j++) { val[j] = NEG; idx[j] = 0; }

#pragma unroll
        for (int e = 0; e < N_EXP; e++) {
            float cv = row[e] * SCALE + bias_sm[e];
            int   ci = e;
#pragma unroll
            for (int j = 0; j < 9; j++) {
                if (cv > val[j]) {
                    float tv = val[j]; val[j] = cv; cv = tv;
                    int   ti = idx[j]; idx[j] = ci; ci = ti;
                }
            }
        }

        float ming = val[0] - val[1];
#pragma unroll
        for (int j = 1; j < 8; j++) ming = fminf(ming, val[j] - val[j + 1]);

        float orig[TOP_K];
#pragma unroll
        for (int j = 0; j < TOP_K; j++) orig[j] = val[j] - bias_sm[idx[j]];
        float m = orig[0];
#pragma unroll
        for (int j = 1; j < TOP_K; j++) m = fmaxf(m, orig[j]);
        float ex[TOP_K], ssum = 0.0f;
#pragma unroll
        for (int j = 0; j < TOP_K; j++) { ex[j] = __expf(orig[j] - m); ssum += ex[j]; }
        float inv = 1.0f / ssum;

        float* wout = out + (size_t)tok * TOP_K;
        float* iout = out + (size_t)T * TOP_K + (size_t)tok * TOP_K;
#pragma unroll
        for (int j = 0; j < TOP_K; j++) { wout[j] = ex[j] * inv; iout[j] = (float)idx[j]; }

        if (ming < EPS) {
            int p = atomicAdd(&g_flag_count, 1);
            if (p < MAX_T) g_flags[p] = tok;
        }
    }
}

// ---------------------------------------------------------------------------
// Fixup stage 1 (panel-parallel): block = (batch of 32 tokens, panel of 512 k).
// Exact serial FFMA chain ascending k within the panel (8 staged chunks of
// 64), starting from zero — identical op sequence to the reference panel.
// Thread = 4 experts x 2 tokens. Partials written to g_partial.
// ---------------------------------------------------------------------------
#define FB 32
#define XPITCH 34
__global__ void __launch_bounds__(256) fixup_panel_kernel(
    const float* __restrict__ x, const float* __restrict__ W)
{
    __shared__ __align__(16) float Wp[64][68];
    __shared__ __align__(16) float Xt[64][XPITCH];

    const int t = threadIdx.x;

    int F = g_flag_count;
    if (F > MAX_T) F = MAX_T;
    const int nb = (F + FB - 1) / FB;

    const int e0 = (t & 15) * 4;
    const int tq = t >> 4;
    const int sx_tok = t >> 3;
    const int sx_k0  = (t & 7) * 8;

    for (int it = blockIdx.x; it < nb * 4; it += gridDim.x) {
        const int b = it >> 2;
        const int p = it & 3;          // panel 0..3 -> k in [p*512, p*512+512)

        float accP[2][4];
#pragma unroll
        for (int i = 0; i < 2; i++)
#pragma unroll
            for (int q = 0; q < 4; q++) accP[i][q] = 0.f;

        for (int kc = p * 8; kc < p * 8 + 8; kc++) {
            __syncthreads();
            {
                int s2 = b * FB + sx_tok;
                int gt = g_flags[(s2 < F) ? s2 : (F - 1)];
                const float* xp = x + (size_t)gt * D_MODEL + kc * 64 + sx_k0;
                float4 v0 = *reinterpret_cast<const float4*>(xp);
                float4 v1 = *reinterpret_cast<const float4*>(xp + 4);
                Xt[sx_k0 + 0][sx_tok] = v0.x; Xt[sx_k0 + 1][sx_tok] = v0.y;
                Xt[sx_k0 + 2][sx_tok] = v0.z; Xt[sx_k0 + 3][sx_tok] = v0.w;
                Xt[sx_k0 + 4][sx_tok] = v1.x; Xt[sx_k0 + 5][sx_tok] = v1.y;
                Xt[sx_k0 + 6][sx_tok] = v1.z; Xt[sx_k0 + 7][sx_tok] = v1.w;
            }
#pragma unroll
            for (int j = 0; j < 4; j++) {
                int idx = t + 256 * j;
                int xe  = idx >> 4;
                int kq  = (idx & 15) * 4;
                float4 w = *reinterpret_cast<const float4*>(
                    W + (size_t)xe * D_MODEL + kc * 64 + kq);
                Wp[kq + 0][xe] = w.x;
                Wp[kq + 1][xe] = w.y;
                Wp[kq + 2][xe] = w.z;
                Wp[kq + 3][xe] = w.w;
            }
            __syncthreads();
#pragma unroll 4
            for (int k = 0; k < 64; k++) {
                float4 wvv = *reinterpret_cast<const float4*>(&Wp[k][e0]);
                float2 xvv = *reinterpret_cast<const float2*>(&Xt[k][tq * 2]);
                accP[0][0] = __fmaf_rn(xvv.x, wvv.x, accP[0][0]);
                accP[0][1] = __fmaf_rn(xvv.x, wvv.y, accP[0][1]);
                accP[0][2] = __fmaf_rn(xvv.x, wvv.z, accP[0][2]);
                accP[0][3] = __fmaf_rn(xvv.x, wvv.w, accP[0][3]);
                accP[1][0] = __fmaf_rn(xvv.y, wvv.x, accP[1][0]);
                accP[1][1] = __fmaf_rn(xvv.y, wvv.y, accP[1][1]);
                accP[1][2] = __fmaf_rn(xvv.y, wvv.z, accP[1][2]);
                accP[1][3] = __fmaf_rn(xvv.y, wvv.w, accP[1][3]);
            }
        }
        // write partials: g_partial[((b*32 + tok)*4 + p)*64 + e]
#pragma unroll
        for (int i = 0; i < 2; i++) {
            float4 v = make_float4(accP[i][0], accP[i][1], accP[i][2], accP[i][3]);
            *reinterpret_cast<float4*>(
                &g_partial[(((size_t)b * FB + tq * 2 + i) * 4 + p) * 64 + e0]) = v;
        }
        __syncthreads();
    }
}

// ---------------------------------------------------------------------------
// Fixup stage 2 (combine): per flagged token, sum 4 panel partials in
// ascending order (__fadd_rn) — the exact reference sequence — then
// x SCALE, exact top-k, softmax, write. Resets flag counter via ticket.
// ---------------------------------------------------------------------------
__global__ void __launch_bounds__(256) fixup_combine_kernel(
    const float* __restrict__ bias, float* __restrict__ out, int T)
{
    __shared__ float Lg[FB][66];
    __shared__ float bias_f[N_EXP];

    const int t = threadIdx.x;
    if (t < N_EXP) bias_f[t] = bias[t];

    int F = g_flag_count;
    if (F > MAX_T) F = MAX_T;
    const int nb = (F + FB - 1) / FB;

    const int tok_s = t >> 3;          // token slot 0..31
    const int eg    = (t & 7) * 8;     // 8 experts per thread

    for (int b = blockIdx.x; b < nb; b += gridDim.x) {
        __syncthreads();
#pragma unroll
        for (int u = 0; u < 2; u++) {
            int e = eg + u * 4;
            const float* gp =
                &g_partial[(((size_t)b * FB + tok_s) * 4 + 0) * 64 + e];
            float4 p0 = *reinterpret_cast<const float4*>(gp);
            float4 p1 = *reinterpret_cast<const float4*>(gp + 64);
            float4 p2 = *reinterpret_cast<const float4*>(gp + 128);
            float4 p3 = *reinterpret_cast<const float4*>(gp + 192);
            Lg[tok_s][e + 0] = __fmul_rn(__fadd_rn(__fadd_rn(__fadd_rn(p0.x, p1.x), p2.x), p3.x), SCALE);
            Lg[tok_s][e + 1] = __fmul_rn(__fadd_rn(__fadd_rn(__fadd_rn(p0.y, p1.y), p2.y), p3.y), SCALE);
            Lg[tok_s][e + 2] = __fmul_rn(__fadd_rn(__fadd_rn(__fadd_rn(p0.z, p1.z), p2.z), p3.z), SCALE);
            Lg[tok_s][e + 3] = __fmul_rn(__fadd_rn(__fadd_rn(__fadd_rn(p0.w, p1.w), p2.w), p3.w), SCALE);
        }
        __syncthreads();

        if (t < FB && b * FB + t < F) {
            const int tok = g_flags[b * FB + t];
            const float* row = &Lg[t][0];
            unsigned long long used = 0ull;
            int sel[TOP_K]; float sl[TOP_K];
            for (int k = 0; k < TOP_K; k++) {
                float best = -3.0e38f; int bi = 0;
                for (int e = 0; e < N_EXP; e++) {
                    if ((used >> e) & 1ull) continue;
                    float bv = __fadd_rn(row[e], bias_f[e]);
                    if (bv > best) { best = bv; bi = e; }
                }
                sel[k] = bi; sl[k] = row[bi];
                used |= (1ull << bi);
            }
            float m = sl[0];
            for (int k = 1; k < TOP_K; k++) m = fmaxf(m, sl[k]);
            float ex[TOP_K], s = 0.0f;
            for (int k = 0; k < TOP_K; k++) { ex[k] = __expf(sl[k] - m); s += ex[k]; }
            float inv = 1.0f / s;
            for (int k = 0; k < TOP_K; k++) {
                out[(size_t)tok * TOP_K + k] = ex[k] * inv;
                out[(size_t)T * TOP_K + (size_t)tok * TOP_K + k] = (float)sel[k];
            }
        }
    }

    // ---- ticket: last block resets the flag counter for the next call ------
    __syncthreads();
    if (t == 0) {
        __threadfence();
        int ticket = atomicAdd(&g_done_count, 1);
        if (ticket == (int)gridDim.x - 1) {
            g_flag_count = 0;
            g_done_count = 0;
            __threadfence();
        }
    }
}

// ---------------------------------------------------------------------------
extern "C" void kernel_launch(void* const* d_in, const int* in_sizes, int n_in,
                              void* d_out, int out_size)
{
    const float* x    = (const float*)d_in[0];
    const float* W    = (const float*)d_in[1];
    const float* bias = (const float*)d_in[2];
    float* out        = (float*)d_out;

    int T = in_sizes[0] / D_MODEL;  // 16384

    router_mma_kernel<<<T / CTA_TOK, 256>>>(x, W, bias, out, T);
    fixup_panel_kernel<<<592, 256>>>(x, W);
    fixup_combine_kernel<<<128, 256>>>(bias, out, T);
}